// round 6
// baseline (speedup 1.0000x reference)
#include <cuda_runtime.h>

// GoalEncoder: 20-step LSTM, B=65536, H=128. Folded input path, fp32x2 packed math.
// R5: fix "too many resources requested for launch" — bound registers on BOTH
// kernels (prep was launched at 512 threads with no launch_bounds) and halve
// per-thread accumulator state (BM 32 -> 16).

#define T_STEPS 20
#define BATCH   65536
#define BM      16        // batch rows per CTA
#define HSTRIDE 18        // padded row stride of transposed h buffer (BM + 2)

typedef unsigned long long u64;

// Prepacked recurrent weights: W4[(k*128+hu)*4 + q] = W_hh[(q*128+hu)*128 + k]
__device__ float g_W4[128 * 128 * 4];
// Folded input-path constants per hu: [hu*12 + {0..3:wx, 4..7:wy, 8..11:bias}] (q = i,f,g,o)
__device__ float g_WB[128 * 12];

__device__ __forceinline__ u64 pk2(float lo, float hi) {
    u64 r; asm("mov.b64 %0, {%1, %2};" : "=l"(r) : "f"(lo), "f"(hi)); return r;
}
__device__ __forceinline__ void upk2(u64 v, float &lo, float &hi) {
    asm("mov.b64 {%0, %1}, %2;" : "=f"(lo), "=f"(hi) : "l"(v));
}
__device__ __forceinline__ u64 ffma2(u64 a, u64 b, u64 c) {
    u64 d; asm("fma.rn.f32x2 %0, %1, %2, %3;" : "=l"(d) : "l"(a), "l"(b), "l"(c)); return d;
}

// Fast nonlinearities (EX2 + RCP MUFU, ~1e-6 rel err; well-behaved at extremes)
__device__ __forceinline__ float sigf(float x) {
    return __fdividef(1.0f, 1.0f + __expf(-x));
}
__device__ __forceinline__ float tanh_f(float x) {
    return fmaf(2.0f, sigf(2.0f * x), -1.0f);
}

// ---------------------------------------------------------------------------
// Prep: fold embedding into input weights; transpose/pack W_hh for the mainloop.
// Register-light by construction: 256 threads, bounded, limited unroll.
// ---------------------------------------------------------------------------
__global__ void __launch_bounds__(256)
prep_kernel(const float* __restrict__ W_emb, const float* __restrict__ b_emb,
            const float* __restrict__ W_ih,  const float* __restrict__ W_hh,
            const float* __restrict__ b_ih,  const float* __restrict__ b_hh)
{
    const int stride = gridDim.x * blockDim.x;
    const int tid = blockIdx.x * blockDim.x + threadIdx.x;

    // W4[k][hu][q] = W_hh[q*128+hu][k]
    for (int i = tid; i < 128 * 128 * 4; i += stride) {
        int q  = i & 3;
        int hu = (i >> 2) & 127;
        int k  = i >> 9;
        g_W4[i] = W_hh[((q << 7) + hu) * 128 + k];
    }

    // Folded input path: gate_x[j] = wx[j]*ox + wy[j]*oy + bias[j]
    for (int j = tid; j < 512; j += stride) {
        float wx = 0.f, wy = 0.f, bb = b_ih[j] + b_hh[j];
        #pragma unroll 4
        for (int d = 0; d < 64; ++d) {
            float w = W_ih[j * 64 + d];
            wx = fmaf(w, W_emb[d * 2 + 0], wx);
            wy = fmaf(w, W_emb[d * 2 + 1], wy);
            bb = fmaf(w, b_emb[d], bb);
        }
        int q = j >> 7, hu = j & 127;
        g_WB[hu * 12 + q]     = wx;
        g_WB[hu * 12 + 4 + q] = wy;
        g_WB[hu * 12 + 8 + q] = bb;
    }
}

// ---------------------------------------------------------------------------
// Main: one CTA = 16 batch rows for all 20 steps.
// 256 threads: hu = tid&127 (hidden unit, owns i/f/g/o of that unit),
//              rg = tid>>7  (row half: rows rg*8 .. rg*8+7, as 4 f32x2 pairs).
// ---------------------------------------------------------------------------
__global__ void __launch_bounds__(256)
lstm_kernel(const float* __restrict__ obs, const float* __restrict__ h0,
            const float* __restrict__ c0, float* __restrict__ out)
{
    __shared__ __align__(16) float hbuf[2][128 * HSTRIDE];  // [k][row] transposed, padded
    __shared__ float obsbuf[2][2 * BM];                     // per-step (ox,oy) stage

    const int tid  = threadIdx.x;
    const int hu   = tid & 127;
    const int rg   = tid >> 7;
    const int base = blockIdx.x * BM;

    // Per-thread folded input constants
    float wx[4], wy[4], bb[4];
    {
        const float* wb = &g_WB[hu * 12];
        #pragma unroll
        for (int q = 0; q < 4; ++q) { wx[q] = wb[q]; wy[q] = wb[4 + q]; bb[q] = wb[8 + q]; }
    }

    // Load h0 transposed into hbuf[0]  (coalesced global reads)
    for (int i = tid; i < BM * 128; i += 256) {
        int r = i >> 7, k = i & 127;
        hbuf[0][k * HSTRIDE + r] = h0[(base + r) * 128 + k];
    }
    // Stage obs for t=0
    if (tid < 2 * BM) obsbuf[0][tid] = obs[base * 2 + tid];

    // c state in registers, pair-packed over rows (4 pairs = 8 rows per thread)
    u64 c2[4];
    #pragma unroll
    for (int p = 0; p < 4; ++p) {
        int r0 = rg * 8 + 2 * p;
        c2[p] = pk2(c0[(base + r0) * 128 + hu], c0[(base + r0 + 1) * 128 + hu]);
    }
    __syncthreads();

    int cur = 0;
    for (int t = 0; t < T_STEPS; ++t) {
        // ---- init gate accumulators with folded input path ----
        u64 acc[4][4];
        const float* ob = obsbuf[t & 1];
        #pragma unroll
        for (int p = 0; p < 4; ++p) {
            int r0 = rg * 8 + 2 * p;
            float ox0 = ob[2 * r0 + 0], oy0 = ob[2 * r0 + 1];
            float ox1 = ob[2 * r0 + 2], oy1 = ob[2 * r0 + 3];
            #pragma unroll
            for (int q = 0; q < 4; ++q) {
                float a0 = fmaf(wx[q], ox0, fmaf(wy[q], oy0, bb[q]));
                float a1 = fmaf(wx[q], ox1, fmaf(wy[q], oy1, bb[q]));
                acc[q][p] = pk2(a0, a1);
            }
        }

        // ---- recurrent GEMM: gates += h @ W_hh^T  (f32x2 packed over row pairs) ----
        const float*  hrow = hbuf[cur] + rg * 8;
        const float4* wp   = (const float4*)(g_W4) + hu;
        #pragma unroll 4
        for (int k = 0; k < 128; ++k) {
            float4 w4 = __ldg(wp + k * 128);       // {wi,wf,wg,wo} for (k,hu), coalesced
            u64 wi = pk2(w4.x, w4.x);
            u64 wf = pk2(w4.y, w4.y);
            u64 wg = pk2(w4.z, w4.z);
            u64 wo = pk2(w4.w, w4.w);
            const float* hk = hrow + k * HSTRIDE;  // broadcast LDS across the warp
            #pragma unroll
            for (int p = 0; p < 4; ++p) {
                u64 h2 = *(const u64*)(hk + 2 * p);
                acc[0][p] = ffma2(h2, wi, acc[0][p]);
                acc[1][p] = ffma2(h2, wf, acc[1][p]);
                acc[2][p] = ffma2(h2, wg, acc[2][p]);
                acc[3][p] = ffma2(h2, wo, acc[3][p]);
            }
        }

        // Prefetch next step's obs while gates settle
        if (t < T_STEPS - 1 && tid < 2 * BM)
            obsbuf[(t + 1) & 1][tid] = obs[(size_t)(t + 1) * (BATCH * 2) + base * 2 + tid];

        // ---- LSTM pointwise update (thread-local: this thread owns i,f,g,o of hu) ----
        float* hnext = hbuf[cur ^ 1];
        #pragma unroll
        for (int p = 0; p < 4; ++p) {
            float i0, i1, f0, f1, g0, g1, o0, o1, cl, ch;
            upk2(acc[0][p], i0, i1);
            upk2(acc[1][p], f0, f1);
            upk2(acc[2][p], g0, g1);
            upk2(acc[3][p], o0, o1);
            upk2(c2[p], cl, ch);
            float cn0 = sigf(f0) * cl + sigf(i0) * tanh_f(g0);
            float cn1 = sigf(f1) * ch + sigf(i1) * tanh_f(g1);
            c2[p] = pk2(cn0, cn1);
            float hn0 = sigf(o0) * tanh_f(cn0);
            float hn1 = sigf(o1) * tanh_f(cn1);
            int r0 = rg * 8 + 2 * p;
            if (t == T_STEPS - 1) {
                out[(base + r0)     * 128 + hu] = hn0;   // coalesced across lanes
                out[(base + r0 + 1) * 128 + hu] = hn1;
            } else {
                // transposed store for next step; 8B aligned, 2-way bank conflict max
                *(u64*)(hnext + hu * HSTRIDE + r0) = pk2(hn0, hn1);
            }
        }
        __syncthreads();
        cur ^= 1;
    }
}

// ---------------------------------------------------------------------------
// Launch. Inputs per metadata order:
// 0 obs_goal [20,65536,2], 1 h0 [B,128], 2 c0 [B,128], 3 W_emb [64,2],
// 4 b_emb [64], 5 W_ih [512,64], 6 W_hh [512,128], 7 b_ih [512], 8 b_hh [512]
// Output: float32 [65536,128]
// ---------------------------------------------------------------------------
extern "C" void kernel_launch(void* const* d_in, const int* in_sizes, int n_in,
                              void* d_out, int out_size)
{
    const float* obs   = (const float*)d_in[0];
    const float* h0    = (const float*)d_in[1];
    const float* c0    = (const float*)d_in[2];
    const float* W_emb = (const float*)d_in[3];
    const float* b_emb = (const float*)d_in[4];
    const float* W_ih  = (const float*)d_in[5];
    const float* W_hh  = (const float*)d_in[6];
    const float* b_ih  = (const float*)d_in[7];
    const float* b_hh  = (const float*)d_in[8];

    prep_kernel<<<96, 256>>>(W_emb, b_emb, W_ih, W_hh, b_ih, b_hh);
    lstm_kernel<<<BATCH / BM, 256>>>(obs, h0, c0, (float*)d_out);
}

// round 8
// speedup vs baseline: 1.5841x; 1.5841x over previous
#include <cuda_runtime.h>
#include <cuda_bf16.h>

// GoalEncoder R8: split-bf16 LSTM on mma.sync.m16n8k16 (portable sm_103 HMMA path).
// gates[128,512] = (h_hi+h_lo)[128,128] @ (W_hi+W_lo)^T via 3 bf16 MMA products.
// W prepacked in exact B-fragment order; streamed via coalesced LDG (L2-resident).
// h double-buffered in SMEM (hi/lo bf16 tiles), ldmatrix-fed. c in registers.

#define T_STEPS 20
#define BATCH   65536

typedef unsigned int u32;
typedef unsigned short u16;

// ---- prepacked device globals ----
__device__ uint2  g_WFhi[16384];   // [kt(8)][nf(64)][lane(32)] b-frags of W_hi
__device__ uint2  g_WFlo[16384];   // same for W_lo (bf16 residual)
__device__ float4 g_WBx[128];      // folded input path per hu: (wx for q=i,f,g,o)
__device__ float4 g_WBy[128];
__device__ float4 g_WBb[128];

// ---- SMEM layout (dynamic) ----
#define A_STRIDE 272               // 128 cols bf16 = 256B + 16B pad (conflict-free ldmatrix)
#define A_TILE   (128 * A_STRIDE)  // 34816
#define OFF_AHI0 0
#define OFF_AHI1 (A_TILE)
#define OFF_ALO0 (2 * A_TILE)
#define OFF_ALO1 (3 * A_TILE)
#define OFF_WBX  (4 * A_TILE)      // 139264
#define OFF_WBY  (OFF_WBX + 2048)
#define OFF_WBB  (OFF_WBX + 4096)
#define SMEM_DYN (OFF_WBX + 6144)  // 145408 bytes

__device__ __forceinline__ u32 smem_u32(const void* p) {
    u32 a;
    asm("{ .reg .u64 t; cvta.to.shared.u64 t, %1; cvt.u32.u64 %0, t; }" : "=r"(a) : "l"(p));
    return a;
}
__device__ __forceinline__ void ldmA(u32* r, u32 addr) {
    asm volatile("ldmatrix.sync.aligned.m8n8.x4.shared.b16 {%0,%1,%2,%3}, [%4];"
        : "=r"(r[0]), "=r"(r[1]), "=r"(r[2]), "=r"(r[3]) : "r"(addr));
}
__device__ __forceinline__ void mma16816(float* d, const u32* a, uint2 b) {
    asm volatile("mma.sync.aligned.m16n8k16.row.col.f32.bf16.bf16.f32 "
        "{%0,%1,%2,%3}, {%4,%5,%6,%7}, {%8,%9}, {%0,%1,%2,%3};"
        : "+f"(d[0]), "+f"(d[1]), "+f"(d[2]), "+f"(d[3])
        : "r"(a[0]), "r"(a[1]), "r"(a[2]), "r"(a[3]), "r"(b.x), "r"(b.y));
}
__device__ __forceinline__ float sigf(float x) { return __fdividef(1.f, 1.f + __expf(-x)); }
__device__ __forceinline__ float tanh_f(float x) { return fmaf(2.f, sigf(2.f * x), -1.f); }

// ---------------------------------------------------------------------------
// Prep: pack W_hh (gate-interleaved n = 4*hu+q) into b-fragment order, split
// bf16 hi/lo; fold embedding+biases into per-hu input constants.
// b-frag layout (m16n8k16, row.col): lane l: n = nf*8 + (l>>2); b0 = W[n][k0..k0+1],
// b1 = W[n][k0+8..k0+9] with k0 = kt*16 + (l&3)*2.
// ---------------------------------------------------------------------------
__global__ void __launch_bounds__(256)
prep_kernel(const float* __restrict__ W_emb, const float* __restrict__ b_emb,
            const float* __restrict__ W_ih,  const float* __restrict__ W_hh,
            const float* __restrict__ b_ih,  const float* __restrict__ b_hh)
{
    const int stride = gridDim.x * blockDim.x;
    const int tid = blockIdx.x * blockDim.x + threadIdx.x;

    for (int idx = tid; idx < 16384; idx += stride) {
        int lane = idx & 31;
        int nfk = idx >> 5;
        int nf = nfk & 63, kt = nfk >> 6;
        int n  = nf * 8 + (lane >> 2);
        int k0 = kt * 16 + (lane & 3) * 2;
        int j  = (n & 3) * 128 + (n >> 2);        // gate-major source row
        const float* wr = W_hh + j * 128;
        float w0 = wr[k0], w1 = wr[k0 + 1], w2 = wr[k0 + 8], w3 = wr[k0 + 9];
        __nv_bfloat16 h0b = __float2bfloat16_rn(w0), h1b = __float2bfloat16_rn(w1);
        __nv_bfloat16 h2b = __float2bfloat16_rn(w2), h3b = __float2bfloat16_rn(w3);
        __nv_bfloat16 l0b = __float2bfloat16_rn(w0 - __bfloat162float(h0b));
        __nv_bfloat16 l1b = __float2bfloat16_rn(w1 - __bfloat162float(h1b));
        __nv_bfloat16 l2b = __float2bfloat16_rn(w2 - __bfloat162float(h2b));
        __nv_bfloat16 l3b = __float2bfloat16_rn(w3 - __bfloat162float(h3b));
        g_WFhi[idx] = make_uint2((u32)__bfloat16_as_ushort(h0b) | ((u32)__bfloat16_as_ushort(h1b) << 16),
                                 (u32)__bfloat16_as_ushort(h2b) | ((u32)__bfloat16_as_ushort(h3b) << 16));
        g_WFlo[idx] = make_uint2((u32)__bfloat16_as_ushort(l0b) | ((u32)__bfloat16_as_ushort(l1b) << 16),
                                 (u32)__bfloat16_as_ushort(l2b) | ((u32)__bfloat16_as_ushort(l3b) << 16));
    }

    for (int hu = tid; hu < 128; hu += stride) {
        float px[4], py[4], pb[4];
        for (int q = 0; q < 4; ++q) {
            int j = q * 128 + hu;
            float wx = 0.f, wy = 0.f, bb = b_ih[j] + b_hh[j];
            #pragma unroll 4
            for (int d = 0; d < 64; ++d) {
                float w = W_ih[j * 64 + d];
                wx = fmaf(w, W_emb[d * 2 + 0], wx);
                wy = fmaf(w, W_emb[d * 2 + 1], wy);
                bb = fmaf(w, b_emb[d], bb);
            }
            px[q] = wx; py[q] = wy; pb[q] = bb;
        }
        g_WBx[hu] = make_float4(px[0], px[1], px[2], px[3]);
        g_WBy[hu] = make_float4(py[0], py[1], py[2], py[3]);
        g_WBb[hu] = make_float4(pb[0], pb[1], pb[2], pb[3]);
    }
}

// ---------------------------------------------------------------------------
// Main: CTA = 128 batch rows, 256 threads (8 warps: wid&1 -> M-half,
// wid>>1 -> N32 slice of each 128-col quarter). 20 sequential steps.
// ---------------------------------------------------------------------------
__global__ void __launch_bounds__(256, 1)
lstm_mma_kernel(const float* __restrict__ obs, const float* __restrict__ h0,
                const float* __restrict__ c0, float* __restrict__ out)
{
    extern __shared__ char sm[];
    const u32 smb = smem_u32(sm);

    const int tid = threadIdx.x;
    const int lid = tid & 31;
    const int wid = tid >> 5;
    const int tig = lid & 3;          // thread-in-group
    const int g   = lid >> 2;         // group id (row within frag)
    const int par = tig & 1;          // row parity (+8 for odd)
    const int mi2 = wid & 1;          // M half
    const int ni4 = wid >> 1;         // N slice (4 n-frags per quarter)
    const int rowbase = mi2 * 64;
    const int cta_row0 = blockIdx.x * 128;

    // stage folded input constants
    if (tid < 128) {
        ((float4*)(sm + OFF_WBX))[tid] = g_WBx[tid];
        ((float4*)(sm + OFF_WBY))[tid] = g_WBy[tid];
        ((float4*)(sm + OFF_WBB))[tid] = g_WBb[tid];
    }

    // A[0] tiles from h0 (bf16 hi/lo split), row-major stride 272B
    for (int i = tid; i < 128 * 128; i += 256) {
        int r = i >> 7, k = i & 127;
        float v = h0[(size_t)(cta_row0 + r) * 128 + k];
        __nv_bfloat16 hb = __float2bfloat16_rn(v);
        __nv_bfloat16 lb = __float2bfloat16_rn(v - __bfloat162float(hb));
        *(u16*)(sm + OFF_AHI0 + r * A_STRIDE + k * 2) = __bfloat16_as_ushort(hb);
        *(u16*)(sm + OFF_ALO0 + r * A_STRIDE + k * 2) = __bfloat16_as_ushort(lb);
    }

    // c0 into registers: cell (qtr, mi, nf) -> (row, hu)
    float c[64];
    #pragma unroll
    for (int qtr = 0; qtr < 4; ++qtr)
        #pragma unroll
        for (int mi = 0; mi < 4; ++mi)
            #pragma unroll
            for (int nf = 0; nf < 4; ++nf) {
                int row = rowbase + mi * 16 + g + 8 * par;
                int hu  = qtr * 32 + (ni4 * 4 + nf) * 2 + (tig >> 1);
                c[qtr * 16 + mi * 4 + nf] = c0[(size_t)(cta_row0 + row) * 128 + hu];
            }
    __syncthreads();

    // ldmatrix per-lane address parts: lanes 0-7: rows 0-7 @k0; 8-15: rows 8-15 @k0;
    // 16-23: rows 0-7 @k0+8; 24-31: rows 8-15 @k0+8
    const u32 a_rs = (u32)((lid & 7) + ((lid >> 3) & 1) * 8);
    const u32 a_ko = (u32)((lid >> 4) * 16);
    const u32 a_lane = (rowbase + a_rs) * A_STRIDE + a_ko;

    #pragma unroll 1
    for (int t = 0; t < T_STEPS; ++t) {
        const int buf = t & 1;
        const u32 ahiB = smb + (buf ? OFF_AHI1 : OFF_AHI0) + a_lane;
        const u32 aloB = smb + (buf ? OFF_ALO1 : OFF_ALO0) + a_lane;
        const int nhi = buf ? OFF_AHI0 : OFF_AHI1;   // next-step buffers
        const int nlo = buf ? OFF_ALO0 : OFF_ALO1;

        // obs (ox,oy) per mi-row for this step
        float ox[4], oy[4];
        #pragma unroll
        for (int mi = 0; mi < 4; ++mi) {
            int row = rowbase + mi * 16 + g + 8 * par;
            float2 o = __ldg((const float2*)(obs + ((size_t)t * BATCH + cta_row0 + row) * 2));
            ox[mi] = o.x; oy[mi] = o.y;
        }

        #pragma unroll
        for (int qtr = 0; qtr < 4; ++qtr) {
            float d[16][4];
            #pragma unroll
            for (int i = 0; i < 16; ++i) { d[i][0] = 0.f; d[i][1] = 0.f; d[i][2] = 0.f; d[i][3] = 0.f; }

            const int fb0 = qtr * 16 + ni4 * 4;          // abs n-frag base for this warp
            uint2 bh[2][4], bl[2][4];                    // 2-deep K prefetch
            #pragma unroll
            for (int pk = 0; pk < 2; ++pk)
                #pragma unroll
                for (int nf = 0; nf < 4; ++nf) {
                    int fi = (pk * 64 + fb0 + nf) * 32 + lid;
                    bh[pk][nf] = __ldg(&g_WFhi[fi]);
                    bl[pk][nf] = __ldg(&g_WFlo[fi]);
                }

            #pragma unroll
            for (int kt = 0; kt < 8; ++kt) {
                const int cur = kt & 1;
                u32 ah[4][4];
                #pragma unroll
                for (int mi = 0; mi < 4; ++mi)
                    ldmA(ah[mi], ahiB + mi * (16 * A_STRIDE) + kt * 32);
                #pragma unroll
                for (int mi = 0; mi < 4; ++mi)
                    #pragma unroll
                    for (int nf = 0; nf < 4; ++nf)
                        mma16816(d[mi * 4 + nf], ah[mi], bh[cur][nf]);   // h_hi * W_hi
                #pragma unroll
                for (int mi = 0; mi < 4; ++mi)
                    #pragma unroll
                    for (int nf = 0; nf < 4; ++nf)
                        mma16816(d[mi * 4 + nf], ah[mi], bl[cur][nf]);   // h_hi * W_lo
                u32 al[4][4];
                #pragma unroll
                for (int mi = 0; mi < 4; ++mi)
                    ldmA(al[mi], aloB + mi * (16 * A_STRIDE) + kt * 32);
                #pragma unroll
                for (int mi = 0; mi < 4; ++mi)
                    #pragma unroll
                    for (int nf = 0; nf < 4; ++nf)
                        mma16816(d[mi * 4 + nf], al[mi], bh[cur][nf]);   // h_lo * W_hi
                if (kt < 6) {
                    #pragma unroll
                    for (int nf = 0; nf < 4; ++nf) {
                        int fi = ((kt + 2) * 64 + fb0 + nf) * 32 + lid;
                        bh[cur][nf] = __ldg(&g_WFhi[fi]);
                        bl[cur][nf] = __ldg(&g_WFlo[fi]);
                    }
                }
            }

            // ---- epilogue: quad assembly via shfl_xor(1), pointwise, h store ----
            #pragma unroll
            for (int nf = 0; nf < 4; ++nf) {
                const int hu = qtr * 32 + (ni4 * 4 + nf) * 2 + (tig >> 1);
                const float4 wx = *(const float4*)(sm + OFF_WBX + hu * 16);
                const float4 wy = *(const float4*)(sm + OFF_WBY + hu * 16);
                const float4 wb = *(const float4*)(sm + OFF_WBB + hu * 16);
                #pragma unroll
                for (int mi = 0; mi < 4; ++mi) {
                    float* dd = d[mi * 4 + nf];
                    float v0 = __shfl_xor_sync(0xffffffffu, dd[0], 1);
                    float v1 = __shfl_xor_sync(0xffffffffu, dd[1], 1);
                    float v2 = __shfl_xor_sync(0xffffffffu, dd[2], 1);
                    float v3 = __shfl_xor_sync(0xffffffffu, dd[3], 1);
                    float gi, gf, gg, go;
                    if (!par) { gi = dd[0]; gf = dd[1]; gg = v0; go = v1; }   // row g
                    else      { gi = v2;   gf = v3;   gg = dd[2]; go = dd[3]; } // row g+8
                    gi = fmaf(wx.x, ox[mi], fmaf(wy.x, oy[mi], gi + wb.x));
                    gf = fmaf(wx.y, ox[mi], fmaf(wy.y, oy[mi], gf + wb.y));
                    gg = fmaf(wx.z, ox[mi], fmaf(wy.z, oy[mi], gg + wb.z));
                    go = fmaf(wx.w, ox[mi], fmaf(wy.w, oy[mi], go + wb.w));
                    const int ci = qtr * 16 + mi * 4 + nf;
                    float cn = fmaf(sigf(gf), c[ci], sigf(gi) * tanh_f(gg));
                    c[ci] = cn;
                    float hn = sigf(go) * tanh_f(cn);
                    const int row = rowbase + mi * 16 + g + 8 * par;
                    if (t == T_STEPS - 1) {
                        out[(size_t)(cta_row0 + row) * 128 + hu] = hn;
                    } else {
                        __nv_bfloat16 hb = __float2bfloat16_rn(hn);
                        __nv_bfloat16 lb = __float2bfloat16_rn(hn - __bfloat162float(hb));
                        *(u16*)(sm + nhi + row * A_STRIDE + hu * 2) = __bfloat16_as_ushort(hb);
                        *(u16*)(sm + nlo + row * A_STRIDE + hu * 2) = __bfloat16_as_ushort(lb);
                    }
                }
            }
        }
        __syncthreads();   // next-step A tiles complete in both hi/lo buffers
    }
}

// ---------------------------------------------------------------------------
// Launch. Inputs: 0 obs [20,B,2], 1 h0 [B,128], 2 c0 [B,128], 3 W_emb, 4 b_emb,
// 5 W_ih, 6 W_hh, 7 b_ih, 8 b_hh. Output float32 [B,128].
// ---------------------------------------------------------------------------
extern "C" void kernel_launch(void* const* d_in, const int* in_sizes, int n_in,
                              void* d_out, int out_size)
{
    const float* obs   = (const float*)d_in[0];
    const float* h0    = (const float*)d_in[1];
    const float* c0    = (const float*)d_in[2];
    const float* W_emb = (const float*)d_in[3];
    const float* b_emb = (const float*)d_in[4];
    const float* W_ih  = (const float*)d_in[5];
    const float* W_hh  = (const float*)d_in[6];
    const float* b_ih  = (const float*)d_in[7];
    const float* b_hh  = (const float*)d_in[8];

    static int attr_done = 0;
    if (!attr_done) {
        cudaFuncSetAttribute(lstm_mma_kernel, cudaFuncAttributeMaxDynamicSharedMemorySize, SMEM_DYN);
        attr_done = 1;
    }

    prep_kernel<<<96, 256>>>(W_emb, b_emb, W_ih, W_hh, b_ih, b_hh);
    lstm_mma_kernel<<<BATCH / 128, 256, SMEM_DYN>>>(obs, h0, c0, (float*)d_out);
}